// round 14
// baseline (speedup 1.0000x reference)
#include <cuda_runtime.h>

#define BB 32
#define SS 2048
#define II 128
#define HH 512
#define OO 64
#define N4 16384            // scan table: tau in [0,4], nearest-neighbor
#define KSC 4096.0f         // N4/4
#define NO 2048             // readout table grid
#define MAGICF 12582912.0f  // 1.5*2^23
#define MAGICI 1262485504   // bits of MAGICF
#define LCH 16
#define NSWEEP 6            // + emission pass = 7 total

#define A_BLKS 256          // dot blocks: 256 thr, 256 rows each (4x64 chunks)
#define B_BLKS 65
#define PREP_BLKS (A_BLKS + B_BLKS)    // 321

#define SCAN_BLKS 32
#define C_BLKS 128          // 16 k-rows x 64 o each
#define K2_BLKS (SCAN_BLKS + C_BLKS)

// ---------------- scratch ----------------
__device__ __align__(16) float  g_dot[BB*SS];
__device__ __align__(16) float2 g_mtau[BB*SS];      // (m, int_bits(ib))
__device__ __align__(16) float  g_G4[N4+260];       // scalar recurrence table
__device__ __align__(16) float  g_Gout[NO*OO];      // readout tables

// tau in [0,4) -> diamond direction (S,C), |S|+|C|=1
__device__ __forceinline__ void tau_to_sc(float tau, float& Sv, float& Cv) {
    if (tau >= 4.0f) tau -= 4.0f;
    int q = (int)tau; if (q > 3) q = 3;
    float u = tau - (float)q;
    switch (q) {
        case 0:  Sv = 1.0f - u; Cv = u;        break;
        case 1:  Sv = -u;       Cv = 1.0f - u; break;
        case 2:  Sv = u - 1.0f; Cv = -u;       break;
        default: Sv = u;        Cv = u - 1.0f; break;
    }
}

// one recurrence step; magic-folded rounding, minimal critical chain
__device__ __forceinline__ void scan_step(float c, float& s, const float* __restrict__ tab,
                                          float& m_out, int& ib_out) {
    float ac  = fabsf(c) + 1e-35f;
    float Kac = KSC * ac;
    float Ap, An, BpM;
    if (c >= 0.f) { Ap =  Kac; An = -Kac; BpM = MAGICF; }
    else          { Ap = -Kac; An =  Kac; BpM = MAGICF + 16384.f; }
    float m = fabsf(s) + ac;
    float r; asm("rcp.approx.f32 %0, %1;" : "=f"(r) : "f"(m));
    bool sp = (s >= 0.f);
    float aqs = sp ? Ap  : An;
    float qaK = sp ? BpM : (MAGICF + 8192.f);
    float y  = fmaf(aqs, r, qaK);          // FMA rounds to integer grid (ulp=1)
    int   ib = __float_as_int(y) - MAGICI; // 0..16384
    float g  = tab[ib];
    m_out = m; ib_out = ib;
    s = fmaf(g, 0.1f * m, 0.9f * s);
}

// ---------------- K1: prep = dot (A, smem transpose) | scan table (B) -----
// A smem: sx[64][33] float4 (33.8KB) + sp[4][64] (1KB) + sir[32] float4 (0.5KB)
#define A_SX_BYTES (64 * 33 * 16)
#define A_SP_BYTES (4 * 64 * 4)
#define SMRAW_BYTES (A_SX_BYTES + A_SP_BYTES + 32 * 16)
__global__ void __launch_bounds__(256)
k_prep(const float* __restrict__ x,  const float* __restrict__ ir,
       const float* __restrict__ ipv, const float* __restrict__ rp,
       const float* __restrict__ rr) {
    __shared__ __align__(16) char smraw[SMRAW_BYTES];
    int bx = blockIdx.x, tid = threadIdx.x;
    int a0 = (int)(((long long)bx       * A_BLKS) / PREP_BLKS);
    int a1 = (int)(((long long)(bx + 1) * A_BLKS) / PREP_BLKS);

    if (a1 > a0) {
        // ---- role A: 256 rows via smem transpose, no SHFL ----
        float4* sx  = (float4*)smraw;                         // [64][33]
        float*  sp  = (float*)(smraw + A_SX_BYTES);           // [4][64]
        float4* sir = (float4*)(smraw + A_SX_BYTES + A_SP_BYTES); // [32]
        if (tid < 32) sir[tid] = ((const float4*)ir)[tid];
        int r0 = a0 * 256;
        int rloc = tid & 63, qq = tid >> 6;                   // quarter 0..3
        const float4* irq = sir + qq * 8;
        #pragma unroll 1
        for (int c = 0; c < 4; ++c) {
            int rc = r0 + c * 64;
            const float4* src = (const float4*)x + (size_t)rc * 32;
            #pragma unroll
            for (int j = 0; j < 8; ++j) {
                int idx = tid + j * 256;                      // 0..2047
                int row = idx >> 5, col = idx & 31;
                sx[row * 33 + col] = src[idx];                // coalesced LDG
            }
            __syncthreads();
            {
                const float4* xr = sx + rloc * 33 + qq * 8;   // conflict-free LDS
                float4 a = make_float4(0.f, 0.f, 0.f, 0.f);
                #pragma unroll
                for (int j = 0; j < 8; ++j) {
                    float4 v = xr[j], w = irq[j];             // w: broadcast
                    a.x = fmaf(v.x, w.x, a.x);
                    a.y = fmaf(v.y, w.y, a.y);
                    a.z = fmaf(v.z, w.z, a.z);
                    a.w = fmaf(v.w, w.w, a.w);
                }
                sp[qq * 64 + rloc] = (a.x + a.y) + (a.z + a.w);
            }
            __syncthreads();
            if (tid < 64)
                g_dot[rc + tid] = (sp[tid] + sp[64 + tid])
                                + (sp[128 + tid] + sp[192 + tid]);
        }
    } else {
        // ---- role B: scan table G4[k] ----
        int nid = bx - a0;
        float* srp = (float*)smraw;
        float* sip = srp + HH;
        float* srr = sip + HH;
        for (int h = tid; h < HH; h += 256) { srp[h]=rp[h]; sip[h]=ipv[h]; srr[h]=rr[h]; }
        __syncthreads();
        int k = nid * 256 + tid;
        if (k < N4 + 8) {
            float Sv, Cv; tau_to_sc((float)k * (4.0f / N4), Sv, Cv);
            float acc = 0.f;
            #pragma unroll 4
            for (int h = 0; h < HH; ++h)
                acc = fmaf(srr[h], fmaxf(fmaf(Sv, srp[h], Cv * sip[h]), 0.f), acc);
            g_G4[k] = acc;
        }
    }
}

// ---------------- K2: scan blocks (0..31) + readout-table GEMM (32..159) --
#define K2_SMEM ((N4 + 8 + SS + 136) * 4)   // 74.3 KB; C role uses 70.7 KB
__global__ void k_scan2(const float* __restrict__ W, const float* __restrict__ rp,
                        const float* __restrict__ ipv) {
    extern __shared__ float sm[];
    int bx = blockIdx.x, tid = threadIdx.x;    // 512 threads

    if (bx < SCAN_BLKS) {
        // ================= scan role =================
        float* tab    = sm;                    // N4+8
        float* sdot   = sm + (N4 + 8);         // SS
        float* sbound = sdot + SS;             // 136
        int b = bx;
        const float4* g4 = (const float4*)g_G4;
        float4* t4 = (float4*)tab;
        for (int i = tid; i < (N4 + 8) / 4; i += 512) t4[i] = g4[i];
        ((float4*)sdot)[tid] = ((const float4*)(g_dot + b * SS))[tid];
        if (tid < 136) sbound[tid] = 0.f;
        __syncthreads();

        float mo; int ibo;
        for (int sw = 0; sw < NSWEEP; ++sw) {
            float s = (tid < 128) ? sbound[tid] : 0.f;
            __syncthreads();
            if (tid < 128) {
                const float* cd = sdot + tid * LCH;
                #pragma unroll
                for (int j = 0; j < LCH; ++j) scan_step(cd[j], s, tab, mo, ibo);
                sbound[tid + 1] = s;
            }
            __syncthreads();
        }
        if (tid < 128) {
            float s = sbound[tid];
            const float* cd = sdot + tid * LCH;
            float2* out = g_mtau + b * SS + tid * LCH;
            #pragma unroll
            for (int j = 0; j < LCH; ++j) {
                scan_step(cd[j], s, tab, mo, ibo);
                out[j] = make_float2(mo, __int_as_float(ibo));
            }
        }
    } else {
        // ================= role C: Gout rows k0..k0+15 =================
        float* su   = sm;                      // [512][16]  32.8 KB
        float* Wsmt = sm + HH * 16;            // [128][66]  33.8 KB
        float* srp  = Wsmt + 128 * 66;         // [512]
        float* sip  = srp + HH;                // [512]
        int c  = bx - SCAN_BLKS;
        int k0 = c * 16;
        if (tid < 128) {
            ((float4*)srp)[tid] = ((const float4*)rp)[tid];
            ((float4*)sip)[tid] = ((const float4*)ipv)[tid];
        }
        __syncthreads();
        {   // su[h][kk] = relu(S*rp + C*ip), kk = 0..15
            int kk = tid & 15, h0 = tid >> 4;  // h0 0..31
            float Sv, Cv; tau_to_sc((float)(k0 + kk) * (4.0f / NO), Sv, Cv);
            #pragma unroll
            for (int j = 0; j < 16; ++j) {
                int h = h0 + 32 * j;
                su[h * 16 + kk] = fmaxf(fmaf(Sv, srp[h], Cv * sip[h]), 0.f);
            }
        }
        int kq = (tid >> 5) & 3, og = tid & 31;
        bool active = (tid < 128);
        float a00=0,a01=0,a10=0,a11=0,a20=0,a21=0,a30=0,a31=0;
        for (int ch = 0; ch < 4; ++ch) {
            int hb = ch * 128;
            __syncthreads();
            {   // stage W[o][hb..hb+127] transposed -> Wsmt[h][o], 512 threads
                int o = tid & 63, hg = tid >> 6;            // hg 0..7, 16 h each
                const float4* wr = (const float4*)(W + (size_t)o * HH + hb + hg * 16);
                #pragma unroll
                for (int j = 0; j < 4; ++j) {
                    float4 wv = wr[j];
                    int h = hg * 16 + j * 4;
                    Wsmt[(h+0)*66 + o] = wv.x; Wsmt[(h+1)*66 + o] = wv.y;
                    Wsmt[(h+2)*66 + o] = wv.z; Wsmt[(h+3)*66 + o] = wv.w;
                }
            }
            __syncthreads();
            if (active) {
                #pragma unroll 4
                for (int h = 0; h < 128; ++h) {
                    float4 u4 = *(const float4*)&su[(hb + h) * 16 + 4 * kq];
                    float2 w2 = *(const float2*)&Wsmt[h * 66 + 2 * og];
                    a00 = fmaf(u4.x, w2.x, a00); a01 = fmaf(u4.x, w2.y, a01);
                    a10 = fmaf(u4.y, w2.x, a10); a11 = fmaf(u4.y, w2.y, a11);
                    a20 = fmaf(u4.z, w2.x, a20); a21 = fmaf(u4.z, w2.y, a21);
                    a30 = fmaf(u4.w, w2.x, a30); a31 = fmaf(u4.w, w2.y, a31);
                }
            }
        }
        if (active) {
            int row = k0 + 4 * kq;
            ((float2*)(g_Gout + (size_t)(row    ) * OO))[og] = make_float2(a00, a01);
            ((float2*)(g_Gout + (size_t)(row + 1) * OO))[og] = make_float2(a10, a11);
            ((float2*)(g_Gout + (size_t)(row + 2) * OO))[og] = make_float2(a20, a21);
            ((float2*)(g_Gout + (size_t)(row + 3) * OO))[og] = make_float2(a30, a31);
        }
    }
}

// ---------------- K3: readout lookup + EMA + bias (512 blocks) ------------
__global__ void k_vo(float* __restrict__ out, const float* __restrict__ bias) {
    __shared__ float2 smt[256];
    int b  = blockIdx.x >> 4;
    int ch = blockIdx.x & 15;
    int t0 = ch * 128;
    int tw = (ch == 0) ? 0 : t0 - 128;
    int nt = t0 + 128 - tw;
    int tid = threadIdx.x;          // 64, one per o
    for (int i = tid; i < nt; i += 64) smt[i] = g_mtau[b * SS + tw + i];
    __syncthreads();
    float bv = bias[tid];
    float acc = 0.f;
    int nwarm = t0 - tw;            // 0 or 128
    for (int jb = 0; jb < nwarm; jb += 16) {
        float gv[16], mm[16];
        #pragma unroll
        for (int q = 0; q < 16; ++q) {
            float2 mt = smt[jb + q];
            int idx = ((__float_as_int(mt.y) + 4) >> 3) & (NO - 1);
            gv[q] = __ldg(&g_Gout[(size_t)idx * OO + tid]);
            mm[q] = mt.x;
        }
        #pragma unroll
        for (int q = 0; q < 16; ++q)
            acc = fmaf(0.9f, acc, gv[q] * (0.1f * mm[q]));
    }
    float* op = out + ((size_t)b * SS + t0) * OO + tid;
    for (int jb = 0; jb < 128; jb += 16) {
        float gv[16], mm[16];
        #pragma unroll
        for (int q = 0; q < 16; ++q) {
            float2 mt = smt[nwarm + jb + q];
            int idx = ((__float_as_int(mt.y) + 4) >> 3) & (NO - 1);
            gv[q] = __ldg(&g_Gout[(size_t)idx * OO + tid]);
            mm[q] = mt.x;
        }
        #pragma unroll
        for (int q = 0; q < 16; ++q) {
            acc = fmaf(0.9f, acc, gv[q] * (0.1f * mm[q]));
            op[(jb + q) * OO] = acc + bv;
        }
    }
}

// ---------------- launch ---------------------------------------------------
extern "C" void kernel_launch(void* const* d_in, const int* in_sizes, int n_in,
                              void* d_out, int out_size) {
    const float* x    = (const float*)d_in[0];
    const float* ip   = (const float*)d_in[1];
    const float* ir   = (const float*)d_in[2];
    const float* rp   = (const float*)d_in[3];
    const float* rr   = (const float*)d_in[4];
    const float* W    = (const float*)d_in[5];
    const float* bias = (const float*)d_in[6];
    float* out = (float*)d_out;

    cudaFuncSetAttribute(k_scan2, cudaFuncAttributeMaxDynamicSharedMemorySize, K2_SMEM);

    k_prep<<<PREP_BLKS, 256>>>(x, ir, ip, rp, rr);
    k_scan2<<<K2_BLKS, 512, K2_SMEM>>>(W, rp, ip);
    k_vo<<<BB*16, 64>>>(out, bias);
}

// round 15
// speedup vs baseline: 1.3291x; 1.3291x over previous
#include <cuda_runtime.h>

#define BB 32
#define SS 2048
#define II 128
#define HH 512
#define OO 64
#define N4 16384            // scan table: tau in [0,4], nearest-neighbor
#define KSC 4096.0f         // N4/4
#define NO 2048             // readout table grid
#define MAGICF 12582912.0f  // 1.5*2^23
#define MAGICI 1262485504   // bits of MAGICF
#define LCH 16
#define NSWEEP 6            // + emission pass = 7 total

#define A_BLKS 512          // dot blocks: 128 thr, 128 rows each (R10-proven)
#define B_BLKS 129
#define PREP_BLKS (A_BLKS + B_BLKS)    // 641

#define SCAN_BLKS 32
#define C_BLKS 128          // 16 k-rows x 64 o each
#define K2_BLKS (SCAN_BLKS + C_BLKS)
#define VO_CBLKS 64         // first 64 C blocks also run the readout tail

// ---------------- scratch ----------------
__device__ __align__(16) float  g_dot[BB*SS];
__device__ __align__(16) float2 g_mtau[BB*SS];      // (m, int_bits(ib))
__device__ __align__(16) float  g_G4[N4+260];       // scalar recurrence table
__device__ __align__(16) float  g_Gout[NO*OO];      // readout tables
__device__ unsigned g_flag[BB];                     // per-batch mtau-ready
__device__ unsigned g_cnt;                          // Gout blocks done

// tau in [0,4) -> diamond direction (S,C), |S|+|C|=1
__device__ __forceinline__ void tau_to_sc(float tau, float& Sv, float& Cv) {
    if (tau >= 4.0f) tau -= 4.0f;
    int q = (int)tau; if (q > 3) q = 3;
    float u = tau - (float)q;
    switch (q) {
        case 0:  Sv = 1.0f - u; Cv = u;        break;
        case 1:  Sv = -u;       Cv = 1.0f - u; break;
        case 2:  Sv = u - 1.0f; Cv = -u;       break;
        default: Sv = u;        Cv = u - 1.0f; break;
    }
}

// one recurrence step; magic-folded rounding, minimal critical chain
__device__ __forceinline__ void scan_step(float c, float& s, const float* __restrict__ tab,
                                          float& m_out, int& ib_out) {
    float ac  = fabsf(c) + 1e-35f;
    float Kac = KSC * ac;
    float Ap, An, BpM;
    if (c >= 0.f) { Ap =  Kac; An = -Kac; BpM = MAGICF; }
    else          { Ap = -Kac; An =  Kac; BpM = MAGICF + 16384.f; }
    float m = fabsf(s) + ac;
    float r; asm("rcp.approx.f32 %0, %1;" : "=f"(r) : "f"(m));
    bool sp = (s >= 0.f);
    float aqs = sp ? Ap  : An;
    float qaK = sp ? BpM : (MAGICF + 8192.f);
    float y  = fmaf(aqs, r, qaK);          // FMA rounds to integer grid (ulp=1)
    int   ib = __float_as_int(y) - MAGICI; // 0..16384
    float g  = tab[ib];
    m_out = m; ib_out = ib;
    s = fmaf(g, 0.1f * m, 0.9f * s);
}

// ---------------- K1: prep = dot (A) | scan table (B), interleaved --------
__global__ void __launch_bounds__(128)
k_prep(const float* __restrict__ x,  const float* __restrict__ ir,
       const float* __restrict__ ipv, const float* __restrict__ rp,
       const float* __restrict__ rr) {
    __shared__ float sb[3*HH];
    int bx = blockIdx.x, tid = threadIdx.x;
    if (bx == 0) {                      // reset sync state for this replay
        if (tid < BB) g_flag[tid] = 0u;
        if (tid == BB) g_cnt = 0u;
    }
    int a0 = (int)(((long long)bx       * A_BLKS) / PREP_BLKS);
    int a1 = (int)(((long long)(bx + 1) * A_BLKS) / PREP_BLKS);

    if (a1 > a0) {
        // ---- role A: dot rows (32 rows/warp, 8-row batches) ----
        int w = tid >> 5, lane = tid & 31;
        int rbase = a0 * 128 + w * 32;
        float4 irv = ((const float4*)ir)[lane];
        #pragma unroll
        for (int i = 0; i < 32; i += 8) {
            float4 a[8];
            #pragma unroll
            for (int q = 0; q < 8; ++q)
                a[q] = ((const float4*)(x + (size_t)(rbase + i + q) * II))[lane];
            float p[8];
            #pragma unroll
            for (int q = 0; q < 8; ++q)
                p[q] = a[q].x*irv.x + a[q].y*irv.y + a[q].z*irv.z + a[q].w*irv.w;
            #pragma unroll
            for (int o = 16; o; o >>= 1) {
                #pragma unroll
                for (int q = 0; q < 8; ++q)
                    p[q] += __shfl_xor_sync(0xFFFFFFFFu, p[q], o);
            }
            if (lane == 0) {
                ((float4*)(g_dot + rbase + i))[0] = make_float4(p[0], p[1], p[2], p[3]);
                ((float4*)(g_dot + rbase + i))[1] = make_float4(p[4], p[5], p[6], p[7]);
            }
        }
    } else {
        // ---- role B: scan table G4[k] ----
        int nid = bx - a0;
        float* srp = sb; float* sip = sb + HH; float* srr = sb + 2*HH;
        for (int h = tid; h < HH; h += 128) { srp[h]=rp[h]; sip[h]=ipv[h]; srr[h]=rr[h]; }
        __syncthreads();
        int k = nid * 128 + tid;
        if (k < N4 + 8) {
            float Sv, Cv; tau_to_sc((float)k * (4.0f / N4), Sv, Cv);
            float acc = 0.f;
            #pragma unroll 4
            for (int h = 0; h < HH; ++h)
                acc = fmaf(srr[h], fmaxf(fmaf(Sv, srp[h], Cv * sip[h]), 0.f), acc);
            g_G4[k] = acc;
        }
    }
}

// ---------------- K2: scan (0..31) + Gout GEMM (32..159) + fused readout --
#define K2_SMEM ((N4 + 8 + SS + 136) * 4)   // 74.3 KB
__global__ void k_scan2(const float* __restrict__ W, const float* __restrict__ rp,
                        const float* __restrict__ ipv,
                        float* __restrict__ out, const float* __restrict__ bias) {
    extern __shared__ float sm[];
    int bx = blockIdx.x, tid = threadIdx.x;    // 512 threads

    if (bx < SCAN_BLKS) {
        // ================= scan role =================
        float* tab    = sm;                    // N4+8
        float* sdot   = sm + (N4 + 8);         // SS
        float* sbound = sdot + SS;             // 136
        int b = bx;
        const float4* g4 = (const float4*)g_G4;
        float4* t4 = (float4*)tab;
        for (int i = tid; i < (N4 + 8) / 4; i += 512) t4[i] = g4[i];
        ((float4*)sdot)[tid] = ((const float4*)(g_dot + b * SS))[tid];
        if (tid < 136) sbound[tid] = 0.f;
        __syncthreads();

        float mo; int ibo;
        for (int sw = 0; sw < NSWEEP; ++sw) {
            float s = (tid < 128) ? sbound[tid] : 0.f;
            __syncthreads();
            if (tid < 128) {
                const float* cd = sdot + tid * LCH;
                #pragma unroll
                for (int j = 0; j < LCH; ++j) scan_step(cd[j], s, tab, mo, ibo);
                sbound[tid + 1] = s;
            }
            __syncthreads();
        }
        if (tid < 128) {
            float s = sbound[tid];
            const float* cd = sdot + tid * LCH;
            float2* outp = g_mtau + b * SS + tid * LCH;
            #pragma unroll
            for (int j = 0; j < LCH; ++j) {
                scan_step(cd[j], s, tab, mo, ibo);
                outp[j] = make_float2(mo, __int_as_float(ibo));
            }
        }
        __threadfence();
        __syncthreads();
        if (tid == 0) atomicExch(&g_flag[b], 1u);   // publish this batch
    } else {
        // ================= role C: Gout rows k0..k0+15 =================
        float* su   = sm;                      // [512][16]  32.8 KB
        float* Wsmt = sm + HH * 16;            // [128][66]  33.8 KB
        float* srp  = Wsmt + 128 * 66;         // [512]
        float* sip  = srp + HH;                // [512]
        int c  = bx - SCAN_BLKS;
        int k0 = c * 16;
        if (tid < 128) {
            ((float4*)srp)[tid] = ((const float4*)rp)[tid];
            ((float4*)sip)[tid] = ((const float4*)ipv)[tid];
        }
        __syncthreads();
        {   // su[h][kk] = relu(S*rp + C*ip), kk = 0..15
            int kk = tid & 15, h0 = tid >> 4;  // h0 0..31
            float Sv, Cv; tau_to_sc((float)(k0 + kk) * (4.0f / NO), Sv, Cv);
            #pragma unroll
            for (int j = 0; j < 16; ++j) {
                int h = h0 + 32 * j;
                su[h * 16 + kk] = fmaxf(fmaf(Sv, srp[h], Cv * sip[h]), 0.f);
            }
        }
        int kq = (tid >> 5) & 3, og = tid & 31;
        bool active = (tid < 128);
        float a00=0,a01=0,a10=0,a11=0,a20=0,a21=0,a30=0,a31=0;
        for (int ch = 0; ch < 4; ++ch) {
            int hb = ch * 128;
            __syncthreads();
            {   // stage W[o][hb..hb+127] transposed -> Wsmt[h][o], 512 threads
                int o = tid & 63, hg = tid >> 6;            // hg 0..7, 16 h each
                const float4* wr = (const float4*)(W + (size_t)o * HH + hb + hg * 16);
                #pragma unroll
                for (int j = 0; j < 4; ++j) {
                    float4 wv = wr[j];
                    int h = hg * 16 + j * 4;
                    Wsmt[(h+0)*66 + o] = wv.x; Wsmt[(h+1)*66 + o] = wv.y;
                    Wsmt[(h+2)*66 + o] = wv.z; Wsmt[(h+3)*66 + o] = wv.w;
                }
            }
            __syncthreads();
            if (active) {
                #pragma unroll 4
                for (int h = 0; h < 128; ++h) {
                    float4 u4 = *(const float4*)&su[(hb + h) * 16 + 4 * kq];
                    float2 w2 = *(const float2*)&Wsmt[h * 66 + 2 * og];
                    a00 = fmaf(u4.x, w2.x, a00); a01 = fmaf(u4.x, w2.y, a01);
                    a10 = fmaf(u4.y, w2.x, a10); a11 = fmaf(u4.y, w2.y, a11);
                    a20 = fmaf(u4.z, w2.x, a20); a21 = fmaf(u4.z, w2.y, a21);
                    a30 = fmaf(u4.w, w2.x, a30); a31 = fmaf(u4.w, w2.y, a31);
                }
            }
        }
        if (active) {
            int row = k0 + 4 * kq;
            ((float2*)(g_Gout + (size_t)(row    ) * OO))[og] = make_float2(a00, a01);
            ((float2*)(g_Gout + (size_t)(row + 1) * OO))[og] = make_float2(a10, a11);
            ((float2*)(g_Gout + (size_t)(row + 2) * OO))[og] = make_float2(a20, a21);
            ((float2*)(g_Gout + (size_t)(row + 3) * OO))[og] = make_float2(a30, a31);
        }
        __threadfence();
        __syncthreads();
        if (tid == 0) atomicAdd(&g_cnt, 1u);   // this Gout tile published

        // ============ fused readout tail (first VO_CBLKS C blocks) ============
        if (c < VO_CBLKS) {
            int gid = tid >> 6, otid = tid & 63;       // 8 groups x 64 threads
            int cid = c * 8 + gid;                     // chunk id 0..511
            int b   = cid >> 4;                        // same b for all gids
            int ch  = cid & 15;
            if (tid == 0) {                            // wait: all Gout + this mtau
                while (atomicAdd(&g_cnt, 0u) < (unsigned)C_BLKS) __nanosleep(64);
                while (atomicAdd(&g_flag[b], 0u) == 0u) __nanosleep(64);
                __threadfence();
            }
            __syncthreads();

            float2* smt = ((float2*)sm) + gid * 256;   // reuse su area (16KB)
            int t0 = ch * 128;
            int tw = (ch == 0) ? 0 : t0 - 128;
            int nt = t0 + 128 - tw;
            for (int i = otid; i < nt; i += 64) smt[i] = g_mtau[b * SS + tw + i];
            __syncthreads();

            float bv = bias[otid];
            float acc = 0.f;
            int nwarm = t0 - tw;                       // 0 or 128
            for (int jb = 0; jb < nwarm; jb += 16) {
                float gv[16], mm[16];
                #pragma unroll
                for (int q = 0; q < 16; ++q) {
                    float2 mt = smt[jb + q];
                    int idx = ((__float_as_int(mt.y) + 4) >> 3) & (NO - 1);
                    gv[q] = __ldg(&g_Gout[(size_t)idx * OO + otid]);
                    mm[q] = mt.x;
                }
                #pragma unroll
                for (int q = 0; q < 16; ++q)
                    acc = fmaf(0.9f, acc, gv[q] * (0.1f * mm[q]));
            }
            float* op = out + ((size_t)b * SS + t0) * OO + otid;
            for (int jb = 0; jb < 128; jb += 16) {
                float gv[16], mm[16];
                #pragma unroll
                for (int q = 0; q < 16; ++q) {
                    float2 mt = smt[nwarm + jb + q];
                    int idx = ((__float_as_int(mt.y) + 4) >> 3) & (NO - 1);
                    gv[q] = __ldg(&g_Gout[(size_t)idx * OO + otid]);
                    mm[q] = mt.x;
                }
                #pragma unroll
                for (int q = 0; q < 16; ++q) {
                    acc = fmaf(0.9f, acc, gv[q] * (0.1f * mm[q]));
                    op[(jb + q) * OO] = acc + bv;
                }
            }
        }
    }
}

// ---------------- launch ---------------------------------------------------
extern "C" void kernel_launch(void* const* d_in, const int* in_sizes, int n_in,
                              void* d_out, int out_size) {
    const float* x    = (const float*)d_in[0];
    const float* ip   = (const float*)d_in[1];
    const float* ir   = (const float*)d_in[2];
    const float* rp   = (const float*)d_in[3];
    const float* rr   = (const float*)d_in[4];
    const float* W    = (const float*)d_in[5];
    const float* bias = (const float*)d_in[6];
    float* out = (float*)d_out;

    cudaFuncSetAttribute(k_scan2, cudaFuncAttributeMaxDynamicSharedMemorySize, K2_SMEM);

    k_prep<<<PREP_BLKS, 128>>>(x, ir, ip, rp, rr);
    k_scan2<<<K2_BLKS, 512, K2_SMEM>>>(W, rp, ip, out, bias);
}

// round 16
// speedup vs baseline: 1.3498x; 1.0155x over previous
#include <cuda_runtime.h>

#define BB 32
#define SS 2048
#define II 128
#define HH 512
#define OO 64
#define N4 16384            // scan table: tau in [0,4], nearest-neighbor
#define KSC 4096.0f         // N4/4
#define NO 2048             // readout table grid
#define MAGICF 12582912.0f  // 1.5*2^23
#define MAGICI 1262485504   // bits of MAGICF
#define LCH 16
#define NSWEEP 5            // + emission pass = 6 total (0.9^96 ~ 4e-5)

#define A_BLKS 512          // dot blocks: 128 thr, 128 rows each (R10-proven)
#define B_BLKS 129
#define PREP_BLKS (A_BLKS + B_BLKS)    // 641

#define SCAN_BLKS 32
#define C_BLKS 256          // 8 k-rows x 64 o each
#define K2_BLKS (SCAN_BLKS + C_BLKS)

// ---------------- scratch ----------------
__device__ __align__(16) float  g_dot[BB*SS];
__device__ __align__(16) float2 g_mtau[BB*SS];      // (m, int_bits(ib))
__device__ __align__(16) float  g_G4[N4+260];       // scalar recurrence table
__device__ __align__(16) float  g_Gout[NO*OO];      // readout tables

// tau in [0,4) -> diamond direction (S,C), |S|+|C|=1
__device__ __forceinline__ void tau_to_sc(float tau, float& Sv, float& Cv) {
    if (tau >= 4.0f) tau -= 4.0f;
    int q = (int)tau; if (q > 3) q = 3;
    float u = tau - (float)q;
    switch (q) {
        case 0:  Sv = 1.0f - u; Cv = u;        break;
        case 1:  Sv = -u;       Cv = 1.0f - u; break;
        case 2:  Sv = u - 1.0f; Cv = -u;       break;
        default: Sv = u;        Cv = u - 1.0f; break;
    }
}

// one recurrence step; magic-folded rounding, minimal critical chain
__device__ __forceinline__ void scan_step(float c, float& s, const float* __restrict__ tab,
                                          float& m_out, int& ib_out) {
    float ac  = fabsf(c) + 1e-35f;
    float Kac = KSC * ac;
    float Ap, An, BpM;
    if (c >= 0.f) { Ap =  Kac; An = -Kac; BpM = MAGICF; }
    else          { Ap = -Kac; An =  Kac; BpM = MAGICF + 16384.f; }
    float m = fabsf(s) + ac;
    float r; asm("rcp.approx.f32 %0, %1;" : "=f"(r) : "f"(m));
    bool sp = (s >= 0.f);
    float aqs = sp ? Ap  : An;
    float qaK = sp ? BpM : (MAGICF + 8192.f);
    float y  = fmaf(aqs, r, qaK);          // FMA rounds to integer grid (ulp=1)
    int   ib = __float_as_int(y) - MAGICI; // 0..16384
    float g  = tab[ib];
    m_out = m; ib_out = ib;
    s = fmaf(g, 0.1f * m, 0.9f * s);
}

// ---------------- K1: prep = dot (A) | scan table (B), interleaved --------
__global__ void __launch_bounds__(128)
k_prep(const float* __restrict__ x,  const float* __restrict__ ir,
       const float* __restrict__ ipv, const float* __restrict__ rp,
       const float* __restrict__ rr) {
    __shared__ float sb[3*HH];
    int bx = blockIdx.x, tid = threadIdx.x;
    int a0 = (int)(((long long)bx       * A_BLKS) / PREP_BLKS);
    int a1 = (int)(((long long)(bx + 1) * A_BLKS) / PREP_BLKS);

    if (a1 > a0) {
        // ---- role A: dot rows (32 rows/warp, 8-row batches) ----
        int w = tid >> 5, lane = tid & 31;
        int rbase = a0 * 128 + w * 32;
        float4 irv = ((const float4*)ir)[lane];
        #pragma unroll
        for (int i = 0; i < 32; i += 8) {
            float4 a[8];
            #pragma unroll
            for (int q = 0; q < 8; ++q)
                a[q] = ((const float4*)(x + (size_t)(rbase + i + q) * II))[lane];
            float p[8];
            #pragma unroll
            for (int q = 0; q < 8; ++q)
                p[q] = a[q].x*irv.x + a[q].y*irv.y + a[q].z*irv.z + a[q].w*irv.w;
            #pragma unroll
            for (int o = 16; o; o >>= 1) {
                #pragma unroll
                for (int q = 0; q < 8; ++q)
                    p[q] += __shfl_xor_sync(0xFFFFFFFFu, p[q], o);
            }
            if (lane == 0) {
                ((float4*)(g_dot + rbase + i))[0] = make_float4(p[0], p[1], p[2], p[3]);
                ((float4*)(g_dot + rbase + i))[1] = make_float4(p[4], p[5], p[6], p[7]);
            }
        }
    } else {
        // ---- role B: scan table G4[k] ----
        int nid = bx - a0;
        float* srp = sb; float* sip = sb + HH; float* srr = sb + 2*HH;
        for (int h = tid; h < HH; h += 128) { srp[h]=rp[h]; sip[h]=ipv[h]; srr[h]=rr[h]; }
        __syncthreads();
        int k = nid * 128 + tid;
        if (k < N4 + 8) {
            float Sv, Cv; tau_to_sc((float)k * (4.0f / N4), Sv, Cv);
            float acc = 0.f;
            #pragma unroll 4
            for (int h = 0; h < HH; ++h)
                acc = fmaf(srr[h], fmaxf(fmaf(Sv, srp[h], Cv * sip[h]), 0.f), acc);
            g_G4[k] = acc;
        }
    }
}

// ---------------- K2: scan blocks (0..31) + readout-table GEMM (32..287) --
#define K2_SMEM ((N4 + 8 + SS + 136) * 4)   // 74.3 KB (scan role); C uses 54.3 KB
__global__ void k_scan2(const float* __restrict__ W, const float* __restrict__ rp,
                        const float* __restrict__ ipv) {
    extern __shared__ float sm[];
    int bx = blockIdx.x, tid = threadIdx.x;    // 512 threads

    if (bx < SCAN_BLKS) {
        // ================= scan role =================
        float* tab    = sm;                    // N4+8
        float* sdot   = sm + (N4 + 8);         // SS
        float* sbound = sdot + SS;             // 136
        int b = bx;
        const float4* g4 = (const float4*)g_G4;
        float4* t4 = (float4*)tab;
        for (int i = tid; i < (N4 + 8) / 4; i += 512) t4[i] = g4[i];
        ((float4*)sdot)[tid] = ((const float4*)(g_dot + b * SS))[tid];
        if (tid < 136) sbound[tid] = 0.f;
        __syncthreads();

        float mo; int ibo;
        for (int sw = 0; sw < NSWEEP; ++sw) {
            float s = (tid < 128) ? sbound[tid] : 0.f;
            __syncthreads();
            if (tid < 128) {
                const float* cd = sdot + tid * LCH;
                #pragma unroll
                for (int j = 0; j < LCH; ++j) scan_step(cd[j], s, tab, mo, ibo);
                sbound[tid + 1] = s;
            }
            __syncthreads();
        }
        if (tid < 128) {
            float s = sbound[tid];
            const float* cd = sdot + tid * LCH;
            float2* out = g_mtau + b * SS + tid * LCH;
            #pragma unroll
            for (int j = 0; j < LCH; ++j) {
                scan_step(cd[j], s, tab, mo, ibo);
                out[j] = make_float2(mo, __int_as_float(ibo));
            }
        }
    } else {
        // ================= role C: Gout rows k0..k0+7 =================
        float* su   = sm;                      // [512][8]   16 KB
        float* Wsmt = sm + HH * 8;             // [128][66]  33.8 KB
        float* srp  = Wsmt + 128 * 66;         // [512]
        float* sip  = srp + HH;                // [512]
        int c  = bx - SCAN_BLKS;
        int k0 = c * 8;
        if (tid < 128) {
            ((float4*)srp)[tid] = ((const float4*)rp)[tid];
            ((float4*)sip)[tid] = ((const float4*)ipv)[tid];
        }
        __syncthreads();
        {   // su[h][kk] = relu(S*rp + C*ip), kk = 0..7
            int kk = tid & 7, h0 = tid >> 3;   // h0 0..63
            float Sv, Cv; tau_to_sc((float)(k0 + kk) * (4.0f / NO), Sv, Cv);
            #pragma unroll
            for (int j = 0; j < 8; ++j) {
                int h = h0 + 64 * j;
                su[h * 8 + kk] = fmaxf(fmaf(Sv, srp[h], Cv * sip[h]), 0.f);
            }
        }
        int kq = (tid >> 5) & 3, og = tid & 31;    // 2k x 2o per thread
        bool active = (tid < 128);
        float a00=0,a01=0,a10=0,a11=0;
        for (int ch = 0; ch < 4; ++ch) {
            int hb = ch * 128;
            __syncthreads();
            {   // stage W[o][hb..hb+127] transposed -> Wsmt[h][o], 512 threads
                int o = tid & 63, hg = tid >> 6;            // hg 0..7, 16 h each
                const float4* wr = (const float4*)(W + (size_t)o * HH + hb + hg * 16);
                #pragma unroll
                for (int j = 0; j < 4; ++j) {
                    float4 wv = wr[j];
                    int h = hg * 16 + j * 4;
                    Wsmt[(h+0)*66 + o] = wv.x; Wsmt[(h+1)*66 + o] = wv.y;
                    Wsmt[(h+2)*66 + o] = wv.z; Wsmt[(h+3)*66 + o] = wv.w;
                }
            }
            __syncthreads();
            if (active) {
                #pragma unroll 4
                for (int h = 0; h < 128; ++h) {
                    float2 u2 = *(const float2*)&su[(hb + h) * 8 + 2 * kq];
                    float2 w2 = *(const float2*)&Wsmt[h * 66 + 2 * og];
                    a00 = fmaf(u2.x, w2.x, a00); a01 = fmaf(u2.x, w2.y, a01);
                    a10 = fmaf(u2.y, w2.x, a10); a11 = fmaf(u2.y, w2.y, a11);
                }
            }
        }
        if (active) {
            int row = k0 + 2 * kq;
            ((float2*)(g_Gout + (size_t)(row    ) * OO))[og] = make_float2(a00, a01);
            ((float2*)(g_Gout + (size_t)(row + 1) * OO))[og] = make_float2(a10, a11);
        }
    }
}

// ---------------- K3: readout lookup + EMA + bias (512 blocks) ------------
__global__ void k_vo(float* __restrict__ out, const float* __restrict__ bias) {
    __shared__ float2 smt[256];
    int b  = blockIdx.x >> 4;
    int ch = blockIdx.x & 15;
    int t0 = ch * 128;
    int tw = (ch == 0) ? 0 : t0 - 128;
    int nt = t0 + 128 - tw;
    int tid = threadIdx.x;          // 64, one per o
    for (int i = tid; i < nt; i += 64) smt[i] = g_mtau[b * SS + tw + i];
    __syncthreads();
    float bv = bias[tid];
    float acc = 0.f;
    int nwarm = t0 - tw;            // 0 or 128
    for (int jb = 0; jb < nwarm; jb += 16) {
        float gv[16], mm[16];
        #pragma unroll
        for (int q = 0; q < 16; ++q) {
            float2 mt = smt[jb + q];
            int idx = ((__float_as_int(mt.y) + 4) >> 3) & (NO - 1);
            gv[q] = __ldg(&g_Gout[(size_t)idx * OO + tid]);
            mm[q] = mt.x;
        }
        #pragma unroll
        for (int q = 0; q < 16; ++q)
            acc = fmaf(0.9f, acc, gv[q] * (0.1f * mm[q]));
    }
    float* op = out + ((size_t)b * SS + t0) * OO + tid;
    for (int jb = 0; jb < 128; jb += 16) {
        float gv[16], mm[16];
        #pragma unroll
        for (int q = 0; q < 16; ++q) {
            float2 mt = smt[nwarm + jb + q];
            int idx = ((__float_as_int(mt.y) + 4) >> 3) & (NO - 1);
            gv[q] = __ldg(&g_Gout[(size_t)idx * OO + tid]);
            mm[q] = mt.x;
        }
        #pragma unroll
        for (int q = 0; q < 16; ++q) {
            acc = fmaf(0.9f, acc, gv[q] * (0.1f * mm[q]));
            op[(jb + q) * OO] = acc + bv;
        }
    }
}

// ---------------- launch ---------------------------------------------------
extern "C" void kernel_launch(void* const* d_in, const int* in_sizes, int n_in,
                              void* d_out, int out_size) {
    const float* x    = (const float*)d_in[0];
    const float* ip   = (const float*)d_in[1];
    const float* ir   = (const float*)d_in[2];
    const float* rp   = (const float*)d_in[3];
    const float* rr   = (const float*)d_in[4];
    const float* W    = (const float*)d_in[5];
    const float* bias = (const float*)d_in[6];
    float* out = (float*)d_out;

    cudaFuncSetAttribute(k_scan2, cudaFuncAttributeMaxDynamicSharedMemorySize, K2_SMEM);

    k_prep<<<PREP_BLKS, 128>>>(x, ir, ip, rp, rr);
    k_scan2<<<K2_BLKS, 512, K2_SMEM>>>(W, rp, ip);
    k_vo<<<BB*16, 64>>>(out, bias);
}